// round 15
// baseline (speedup 1.0000x reference)
#include <cuda_runtime.h>
#include <cstdint>

// TensorProduct, round 15: repack phase DELETED via mma k-permutation.
// Frag position q <-> real k=2q, q+4 <-> 2q+1 (same perm on A and B), so A
// fragments load straight from the raw row-major x1 tile (stride-264 rows,
// bank-conflict-free), fed to mma as fp32 bits (HW truncates to tf32).
// B is rna-tf32, stored with k-pairs contiguous: one LDS.128 = 2 k-steps.
//   Y1  = x1s  @ [a0*W1 | a1*W3]               (K=64, N=128)
//   Y2k = x1vk @ [a0/s3*W2 | a1*W4 | a1/s2*W5]  (K=64, N=192; B shared over k)
// 48-row tiles, 12 warps = 3 row-slabs x 4 w-quarters; double-buffered raw
// with cp.async; in-register x2 epilogue with direct STG.

#define NTH   384
#define TILE  48
#define RRS   264     // raw row stride (words): 8 mod 32 -> phase-conflict-free
#define RS    80      // B row stride (words): 16 mod 32 -> LDS.128 conflict-free

#define RAWBUF (TILE * RRS)                 // 12672 words per raw buffer
#define OFF_B1 (2 * RAWBUF)                 // 25344
#define OFF_B2 (OFF_B1 + 128 * RS)          // 35584
#define SMEM_WORDS (OFF_B2 + 192 * RS)      // 50944
#define SMEM_BYTES (SMEM_WORDS * 4)         // 203776 B

__device__ __forceinline__ uint32_t tf32c(float f) {
    uint32_t u; asm("cvt.rna.tf32.f32 %0, %1;" : "=r"(u) : "f"(f)); return u;
}
// storage position of real k inside B rows: 16-blocks hold 2 k-steps;
// pos = (k & ~15) + 4*((k&7)>>1) + 2*((k>>3)&1) + (k&1)
__device__ __forceinline__ int kpos(int k) {
    return (k & 0x30) + (((k & 7) >> 1) << 2) + (((k >> 3) & 1) << 1) + (k & 1);
}
__device__ __forceinline__ uint32_t smem_u32(const void* p) {
    uint32_t a;
    asm("{ .reg .u64 t; cvta.to.shared.u64 t, %1; cvt.u32.u64 %0, t; }"
        : "=r"(a) : "l"(p));
    return a;
}
__device__ __forceinline__ void mma8(float* c, uint32_t a0, uint32_t a1,
                                     uint32_t a2, uint32_t a3,
                                     uint32_t b0, uint32_t b1) {
    asm volatile(
        "mma.sync.aligned.m16n8k8.row.col.f32.tf32.tf32.f32 "
        "{%0,%1,%2,%3}, {%4,%5,%6,%7}, {%8,%9}, {%0,%1,%2,%3};"
        : "+f"(c[0]), "+f"(c[1]), "+f"(c[2]), "+f"(c[3])
        : "r"(a0), "r"(a1), "r"(a2), "r"(a3), "r"(b0), "r"(b1));
}
__device__ __forceinline__ void cpa16(uint32_t dst, const void* src) {
    asm volatile("cp.async.cg.shared.global [%0], [%1], 16;"
                 :: "r"(dst), "l"(src));
}

__global__ __launch_bounds__(NTH, 1)
void tp_k(const float* __restrict__ x1, const float* __restrict__ x2,
          const float* __restrict__ w1, const float* __restrict__ w2,
          const float* __restrict__ w3, const float* __restrict__ w4,
          const float* __restrict__ w5,
          float* __restrict__ out, int n) {
    extern __shared__ uint32_t sw[];
    const int tid  = threadIdx.x;
    const int lane = tid & 31;
    const int wid  = tid >> 5;
    const int q    = lane & 3;
    const int rsub = lane >> 2;          // 0..7
    const int slab = wid >> 2;           // 0..2  (rows slab*16)
    const int qd   = wid & 3;            // w-quarter: w in [16qd, 16qd+16)

    const float A0   = 0.08838834764831845f;   // sqrt(1/128)
    const float A0S3 = 0.05103103630798288f;   // a0/sqrt(3)
    const float A1   = 0.07216878364870323f;   // sqrt(1/192)
    const float A1R2 = 0.05103103630798288f;   // a1/sqrt(2)

    const int numTiles = (n + TILE - 1) / TILE;
    const uint32_t sbRaw0 = smem_u32(sw);
    const uint32_t sbRaw1 = smem_u32(sw + RAWBUF);

    // ---- prologue: cp.async first tile into raw0 (row stride 264) ----
    if (blockIdx.x < numTiles) {
        int row0 = blockIdx.x * TILE;
        #pragma unroll
        for (int it = 0; it < 8; it++) {
            int idx = tid + it * NTH;               // 3072 16B chunks
            int r = idx >> 6, c = (idx & 63) << 2;
            int grow = row0 + r; if (grow >= n) grow = 0;
            cpa16(sbRaw0 + ((r * RRS + c) << 2), x1 + (size_t)grow * 256 + c);
        }
    }
    asm volatile("cp.async.commit_group;" ::: "memory");

    // ---- stage B: per-thread-aligned n-permutation, k-pair storage ----
    // B1: n = 32*qd' + 8*w' + 2*q' + m   (m=0 -> a0*W1 (y1), m=1 -> a1*W3 (y3))
    for (int i = tid; i < 128 * 64; i += NTH) {
        int nn = i >> 6, k = i & 63;
        int qdd = nn >> 5, nl = nn & 31;
        int wp = nl >> 3, rem = nl & 7, qq = rem >> 1, m = rem & 1;
        int w = 16 * qdd + 4 * qq + wp;
        float v = m ? A1 * w3[k * 64 + w] : A0 * w1[k * 64 + w];
        sw[OFF_B1 + nn * RS + kpos(k)] = tf32c(v);
    }
    // B2: n = 48*qd' + 8*t + 2*q' + j ; s=2t+j; w'=s/3; m=s%3
    for (int i = tid; i < 192 * 64; i += NTH) {
        int nn = i >> 6, k = i & 63;
        int qdd = nn / 48, nl = nn - 48 * qdd;
        int t = nl >> 3, rem = nl & 7, qq = rem >> 1, j = rem & 1;
        int s = 2 * t + j, wp = s / 3, m = s - 3 * wp;
        int w = 16 * qdd + 4 * qq + wp;
        float v = (m == 0) ? A0S3 * w2[k * 64 + w]
                : (m == 1) ? A1 * w4[k * 64 + w]
                :            A1R2 * w5[k * 64 + w];
        sw[OFF_B2 + nn * RS + kpos(k)] = tf32c(v);
    }

    const int rl0 = slab * 16 + rsub;
    const int wb  = 16 * qd + 4 * q;
    const uint32_t* b1 = sw + OFF_B1 + (32 * qd + rsub) * RS + 4 * q;
    const uint32_t* b2 = sw + OFF_B2 + (48 * qd + rsub) * RS + 4 * q;

    int p = 0;
    for (int tile = blockIdx.x; tile < numTiles; tile += gridDim.x, p ^= 1) {
        const int row0 = tile * TILE;

        // ---- issue next tile's cp.async into the other raw buffer ----
        int ntile = tile + gridDim.x;
        if (ntile < numTiles) {
            int nrow0 = ntile * TILE;
            uint32_t dst = p ? sbRaw0 : sbRaw1;
            #pragma unroll
            for (int it = 0; it < 8; it++) {
                int idx = tid + it * NTH;
                int r = idx >> 6, c = (idx & 63) << 2;
                int grow = nrow0 + r; if (grow >= n) grow = 0;
                cpa16(dst + ((r * RRS + c) << 2), x1 + (size_t)grow * 256 + c);
            }
        }
        asm volatile("cp.async.commit_group;" ::: "memory");
        asm volatile("cp.async.wait_group 1;" ::: "memory");   // tile t ready
        __syncthreads();

        // x2 for this tile's epilogue rows
        float4 xq0 = make_float4(0.f, 0.f, 0.f, 0.f), xq1 = xq0;
        if (row0 + rl0 < n)     xq0 = *(const float4*)(x2 + (size_t)(row0 + rl0) * 4);
        if (row0 + rl0 + 8 < n) xq1 = *(const float4*)(x2 + (size_t)(row0 + rl0 + 8) * 4);

        // ---- mainloop: A straight from raw (fp32 bits), B via LDS.128 ----
        float acc1[4][4];
        float acc2[3][6][4];
        #pragma unroll
        for (int t = 0; t < 4; t++)
            #pragma unroll
            for (int c = 0; c < 4; c++) acc1[t][c] = 0.f;
        #pragma unroll
        for (int kv = 0; kv < 3; kv++)
            #pragma unroll
            for (int t = 0; t < 6; t++)
                #pragma unroll
                for (int c = 0; c < 4; c++) acc2[kv][t][c] = 0.f;

        const uint32_t* rw0 = sw + p * RAWBUF + rl0 * RRS;       // row rl0
        const uint32_t* rw1 = rw0 + 8 * RRS;                     // row rl0+8

        #pragma unroll
        for (int ksp = 0; ksp < 4; ksp++) {          // 2 k-steps per iter
            uint4 Bf1[4], Bf2[6];
            #pragma unroll
            for (int t = 0; t < 4; t++)
                Bf1[t] = *(const uint4*)(b1 + t * 8 * RS + ksp * 16);
            #pragma unroll
            for (int t = 0; t < 6; t++)
                Bf2[t] = *(const uint4*)(b2 + t * 8 * RS + ksp * 16);

            #pragma unroll
            for (int h = 0; h < 2; h++) {
                int kb = ksp * 16 + h * 8 + 2 * q;   // real k base (pair kb,kb+1)
                uint2 sl = *(const uint2*)(rw0 + kb);
                uint2 sh = *(const uint2*)(rw1 + kb);
                // 6 consecutive floats = both k's x 3 vector components
                uint2 L0 = *(const uint2*)(rw0 + 64 + 3 * kb);
                uint2 L1 = *(const uint2*)(rw0 + 64 + 3 * kb + 2);
                uint2 L2 = *(const uint2*)(rw0 + 64 + 3 * kb + 4);
                uint2 M0 = *(const uint2*)(rw1 + 64 + 3 * kb);
                uint2 M1 = *(const uint2*)(rw1 + 64 + 3 * kb + 2);
                uint2 M2 = *(const uint2*)(rw1 + 64 + 3 * kb + 4);

                #pragma unroll
                for (int t = 0; t < 4; t++) {
                    uint32_t bx = h ? Bf1[t].z : Bf1[t].x;
                    uint32_t by = h ? Bf1[t].w : Bf1[t].y;
                    mma8(acc1[t], sl.x, sh.x, sl.y, sh.y, bx, by);
                }
                #pragma unroll
                for (int t = 0; t < 6; t++) {
                    uint32_t bx = h ? Bf2[t].z : Bf2[t].x;
                    uint32_t by = h ? Bf2[t].w : Bf2[t].y;
                    mma8(acc2[0][t], L0.x, M0.x, L1.y, M1.y, bx, by);
                    mma8(acc2[1][t], L0.y, M0.y, L2.x, M2.x, bx, by);
                    mma8(acc2[2][t], L1.x, M1.x, L2.y, M2.y, bx, by);
                }
            }
        }

        // ---- epilogue: combine with x2 in-register, STG.128 direct ----
        #pragma unroll
        for (int p2 = 0; p2 < 2; p2++) {
            int grow = row0 + rl0 + 8 * p2;
            if (grow >= n) continue;
            float xs  = p2 ? xq1.x : xq0.x;
            float xv0 = p2 ? xq1.y : xq0.y;
            float xv1 = p2 ? xq1.z : xq0.z;
            float xv2 = p2 ? xq1.w : xq0.w;
            float os4[4], ov[12];
            #pragma unroll
            for (int wp = 0; wp < 4; wp++) {
                float y1 = acc1[wp][2 * p2 + 0];
                float y3 = acc1[wp][2 * p2 + 1];
                int s0 = 3 * wp,     t0 = s0 >> 1, j0 = s0 & 1;
                int s1 = 3 * wp + 1, t1 = s1 >> 1, j1 = s1 & 1;
                int s2 = 3 * wp + 2, t2 = s2 >> 1, j2 = s2 & 1;
                float y2a = acc2[0][t0][2 * p2 + j0];
                float y2b = acc2[1][t0][2 * p2 + j0];
                float y2c = acc2[2][t0][2 * p2 + j0];
                float y4a = acc2[0][t1][2 * p2 + j1];
                float y4b = acc2[1][t1][2 * p2 + j1];
                float y4c = acc2[2][t1][2 * p2 + j1];
                float y5a = acc2[0][t2][2 * p2 + j2];
                float y5b = acc2[1][t2][2 * p2 + j2];
                float y5c = acc2[2][t2][2 * p2 + j2];

                os4[wp] = xs * y1 + xv0 * y2a + xv1 * y2b + xv2 * y2c;
                ov[3 * wp + 0] = xv0 * y3 + xs * y4a + (y5b * xv2 - y5c * xv1);
                ov[3 * wp + 1] = xv1 * y3 + xs * y4b + (y5c * xv0 - y5a * xv2);
                ov[3 * wp + 2] = xv2 * y3 + xs * y4c + (y5a * xv1 - y5b * xv0);
            }
            float* orow = out + (size_t)grow * 256;
            *(float4*)(orow + wb) = make_float4(os4[0], os4[1], os4[2], os4[3]);
            *(float4*)(orow + 64 + 3 * wb + 0) =
                make_float4(ov[0], ov[1], ov[2], ov[3]);
            *(float4*)(orow + 64 + 3 * wb + 4) =
                make_float4(ov[4], ov[5], ov[6], ov[7]);
            *(float4*)(orow + 64 + 3 * wb + 8) =
                make_float4(ov[8], ov[9], ov[10], ov[11]);
        }
        __syncthreads();   // all reads of raw[p] done before it is refilled
    }
}

extern "C" void kernel_launch(void* const* d_in, const int* in_sizes, int n_in,
                              void* d_out, int out_size) {
    const float* x1 = (const float*)d_in[0];
    const float* x2 = (const float*)d_in[1];
    const float* w1 = (const float*)d_in[2];   // w_ss_s
    const float* w2 = (const float*)d_in[3];   // w_vv_s
    const float* w3 = (const float*)d_in[4];   // w_sv_v
    const float* w4 = (const float*)d_in[5];   // w_vs_v
    const float* w5 = (const float*)d_in[6];   // w_vv_v
    float* out = (float*)d_out;

    int n = in_sizes[0] / 256;
    cudaFuncSetAttribute(tp_k, cudaFuncAttributeMaxDynamicSharedMemorySize,
                         SMEM_BYTES);
    int numTiles = (n + TILE - 1) / TILE;
    int grid = numTiles < 148 ? numTiles : 148;
    tp_k<<<grid, NTH, SMEM_BYTES>>>(x1, x2, w1, w2, w3, w4, w5, out, n);
}

// round 16
// speedup vs baseline: 1.4157x; 1.4157x over previous
#include <cuda_runtime.h>
#include <cuda_fp16.h>
#include <cstdint>

// TensorProduct, round 16: fp16 m16n8k16 mma (fp32 accum). fp16 has an 11-bit
// significand == tf32, so accuracy is unchanged while mma count, tensor-pipe
// time, fragment LDS bytes and B footprint all halve vs round 14.
//   Y1  = x1s  @ [a0*W1 | a1*W3]               (K=64, N=128)
//   Y2k = x1vk @ [a0/s3*W2 | a1*W4 | a1/s2*W5]  (K=64, N=192; B shared over k)
// 48-row tiles, 12 warps = 3 row-slabs x 4 w-quarters, M16x16w each.
// k-pairs packed in fp16x2 words, per-8-word-group permutation [0,4,1,5,2,6,3,7]
// so each thread's (j=q, j=q+4) fragment pair is one LDS.64. Row strides 40
// words (8 mod 32) -> all fragment loads bank-conflict-free per phase.

#define NTH   384
#define TILE  48
#define AST   40                     // A-plane row stride (fp16x2 words)
#define BST   40                     // B row stride
#define PL    (TILE * AST)           // 1920

#define OFF_RAW 0
#define RAW_WORDS (TILE * 256)       // 12288
#define OFF_A   RAW_WORDS
#define OFF_B1  (OFF_A + 4 * PL)     // 19968
#define OFF_B2  (OFF_B1 + 128 * BST) // 25088
#define SMEM_WORDS (OFF_B2 + 192 * BST)   // 32768
#define SMEM_BYTES (SMEM_WORDS * 4)       // 131072

// storage position of k-pair j (=k>>1) within a row: groups of 8 words per
// 16 k's, order [0,4,1,5,2,6,3,7]
__device__ __forceinline__ int posj(int j) {
    return ((j >> 3) << 3) + ((j & 3) << 1) + ((j >> 2) & 1);
}
__device__ __forceinline__ uint32_t pack2(float lo, float hi) {
    __half2 h = __floats2half2_rn(lo, hi);
    return *reinterpret_cast<uint32_t*>(&h);
}
__device__ __forceinline__ uint32_t smem_u32(const void* p) {
    uint32_t a;
    asm("{ .reg .u64 t; cvta.to.shared.u64 t, %1; cvt.u32.u64 %0, t; }"
        : "=r"(a) : "l"(p));
    return a;
}
__device__ __forceinline__ void mma16(float* c, uint32_t a0, uint32_t a1,
                                      uint32_t a2, uint32_t a3,
                                      uint32_t b0, uint32_t b1) {
    asm volatile(
        "mma.sync.aligned.m16n8k16.row.col.f32.f16.f16.f32 "
        "{%0,%1,%2,%3}, {%4,%5,%6,%7}, {%8,%9}, {%0,%1,%2,%3};"
        : "+f"(c[0]), "+f"(c[1]), "+f"(c[2]), "+f"(c[3])
        : "r"(a0), "r"(a1), "r"(a2), "r"(a3), "r"(b0), "r"(b1));
}
__device__ __forceinline__ void cpa16(uint32_t dst, const void* src) {
    asm volatile("cp.async.cg.shared.global [%0], [%1], 16;"
                 :: "r"(dst), "l"(src));
}

__global__ __launch_bounds__(NTH, 1)
void tp_k(const float* __restrict__ x1, const float* __restrict__ x2,
          const float* __restrict__ w1, const float* __restrict__ w2,
          const float* __restrict__ w3, const float* __restrict__ w4,
          const float* __restrict__ w5,
          float* __restrict__ out, int n) {
    extern __shared__ uint32_t sw[];
    const int tid  = threadIdx.x;
    const int lane = tid & 31;
    const int wid  = tid >> 5;
    const int q    = lane & 3;
    const int rsub = lane >> 2;          // 0..7
    const int slab = wid >> 2;           // 0..2  (rows slab*16)
    const int qd   = wid & 3;            // w-quarter: w in [16qd, 16qd+16)

    const float A0   = 0.08838834764831845f;   // sqrt(1/128)
    const float A0S3 = 0.05103103630798288f;   // a0/sqrt(3)
    const float A1   = 0.07216878364870323f;   // sqrt(1/192)
    const float A1R2 = 0.05103103630798288f;   // a1/sqrt(2)

    const int numTiles = (n + TILE - 1) / TILE;
    const uint32_t sbRaw = smem_u32(sw + OFF_RAW);

    // ---- prologue: cp.async first tile into raw (flat 256-word rows) ----
    {
        int row0 = blockIdx.x * TILE;
        #pragma unroll
        for (int it = 0; it < 8; it++) {
            int idx = tid + it * NTH;               // 3072 16B chunks
            int r = idx >> 6, c = (idx & 63) << 2;
            int grow = row0 + r; if (grow >= n) grow = 0;
            cpa16(sbRaw + (idx << 4), x1 + (size_t)grow * 256 + c);
        }
    }
    asm volatile("cp.async.commit_group;" ::: "memory");

    // ---- stage B (fp16 pairs, n-permuted, k-pair-permuted) ----
    // B1: n = 32*qd' + 8*w' + 2*q' + m   (m=0 -> a0*W1 (y1), m=1 -> a1*W3 (y3))
    for (int i = tid; i < 128 * 32; i += NTH) {
        int nn = i >> 5, j = i & 31;
        int qdd = nn >> 5, nl = nn & 31;
        int wp = nl >> 3, rem = nl & 7, qq = rem >> 1, m = rem & 1;
        int w = 16 * qdd + 4 * qq + wp;
        int k0 = 2 * j, k1 = 2 * j + 1;
        float vlo = m ? A1 * w3[k0 * 64 + w] : A0 * w1[k0 * 64 + w];
        float vhi = m ? A1 * w3[k1 * 64 + w] : A0 * w1[k1 * 64 + w];
        sw[OFF_B1 + nn * BST + posj(j)] = pack2(vlo, vhi);
    }
    // B2: n = 48*qd' + 8*t + 2*q' + jj ; s=2t+jj; w'=s/3; m=s%3
    for (int i = tid; i < 192 * 32; i += NTH) {
        int nn = i >> 5, j = i & 31;
        int qdd = nn / 48, nl = nn - 48 * qdd;
        int t = nl >> 3, rem = nl & 7, qq = rem >> 1, jj = rem & 1;
        int s = 2 * t + jj, wp = s / 3, m = s - 3 * wp;
        int w = 16 * qdd + 4 * qq + wp;
        int k0 = 2 * j, k1 = 2 * j + 1;
        float sc = (m == 0) ? A0S3 : (m == 1) ? A1 : A1R2;
        const float* W = (m == 0) ? w2 : (m == 1) ? w4 : w5;
        sw[OFF_B2 + nn * BST + posj(j)] = pack2(sc * W[k0 * 64 + w],
                                                sc * W[k1 * 64 + w]);
    }

    const int rl0 = slab * 16 + rsub;
    const int wb  = 16 * qd + 4 * q;
    const uint32_t* aS  = sw + OFF_A + rl0 * AST + 2 * q;
    const uint32_t* b1p = sw + OFF_B1 + (32 * qd + rsub) * BST + 2 * q;
    const uint32_t* b2p = sw + OFF_B2 + (48 * qd + rsub) * BST + 2 * q;
    const float* rawf = (const float*)(sw + OFF_RAW);

    for (int tile = blockIdx.x; tile < numTiles; tile += gridDim.x) {
        const int row0 = tile * TILE;

        // ---- wait raw; repack to fp16 planes; prefetch x2 ----
        asm volatile("cp.async.wait_group 0;" ::: "memory");
        __syncthreads();   // raw visible; previous mainloop done with planes

        float4 xq0 = make_float4(0.f, 0.f, 0.f, 0.f), xq1 = xq0;
        if (row0 + rl0 < n)     xq0 = *(const float4*)(x2 + (size_t)(row0 + rl0) * 4);
        if (row0 + rl0 + 8 < n) xq1 = *(const float4*)(x2 + (size_t)(row0 + rl0 + 8) * 4);

        #pragma unroll
        for (int it = 0; it < 4; it++) {
            int task = tid + it * NTH;           // 1536 = 48 rows x 32 j
            int r = task >> 5, j = task & 31;
            const float* rp = rawf + r * 256;
            float s0 = rp[2 * j], s1 = rp[2 * j + 1];
            float b0 = rp[64 + 6 * j + 0], b1 = rp[64 + 6 * j + 1];
            float b2 = rp[64 + 6 * j + 2], b3 = rp[64 + 6 * j + 3];
            float b4 = rp[64 + 6 * j + 4], b5 = rp[64 + 6 * j + 5];
            int ao = r * AST + posj(j);
            sw[OFF_A + 0 * PL + ao] = pack2(s0, s1);   // scalar plane
            sw[OFF_A + 1 * PL + ao] = pack2(b0, b3);   // v component 0
            sw[OFF_A + 2 * PL + ao] = pack2(b1, b4);   // v component 1
            sw[OFF_A + 3 * PL + ao] = pack2(b2, b5);   // v component 2
        }
        __syncthreads();   // planes ready; raw free

        // ---- issue next tile's cp.async (hidden under mainloop) ----
        int ntile = tile + gridDim.x;
        if (ntile < numTiles) {
            int nrow0 = ntile * TILE;
            #pragma unroll
            for (int it = 0; it < 8; it++) {
                int idx = tid + it * NTH;
                int r = idx >> 6, c = (idx & 63) << 2;
                int grow = nrow0 + r; if (grow >= n) grow = 0;
                cpa16(sbRaw + (idx << 4), x1 + (size_t)grow * 256 + c);
            }
        }
        asm volatile("cp.async.commit_group;" ::: "memory");

        // ---- mainloop: 4 k16-steps, 22 mma each ----
        float acc1[4][4];
        float acc2[3][6][4];
        #pragma unroll
        for (int t = 0; t < 4; t++)
            #pragma unroll
            for (int c = 0; c < 4; c++) acc1[t][c] = 0.f;
        #pragma unroll
        for (int kv = 0; kv < 3; kv++)
            #pragma unroll
            for (int t = 0; t < 6; t++)
                #pragma unroll
                for (int c = 0; c < 4; c++) acc2[kv][t][c] = 0.f;

        #pragma unroll
        for (int g = 0; g < 4; g++) {
            uint2 s0 = *(const uint2*)(aS + g * 8);
            uint2 s1 = *(const uint2*)(aS + 8 * AST + g * 8);
            uint2 vl[3], vh[3];
            #pragma unroll
            for (int kv = 0; kv < 3; kv++) {
                vl[kv] = *(const uint2*)(aS + (kv + 1) * PL + g * 8);
                vh[kv] = *(const uint2*)(aS + (kv + 1) * PL + 8 * AST + g * 8);
            }
            #pragma unroll
            for (int t = 0; t < 4; t++) {
                uint2 b = *(const uint2*)(b1p + t * 8 * BST + g * 8);
                mma16(acc1[t], s0.x, s1.x, s0.y, s1.y, b.x, b.y);
            }
            #pragma unroll
            for (int t = 0; t < 6; t++) {
                uint2 b = *(const uint2*)(b2p + t * 8 * BST + g * 8);
                mma16(acc2[0][t], vl[0].x, vh[0].x, vl[0].y, vh[0].y, b.x, b.y);
                mma16(acc2[1][t], vl[1].x, vh[1].x, vl[1].y, vh[1].y, b.x, b.y);
                mma16(acc2[2][t], vl[2].x, vh[2].x, vl[2].y, vh[2].y, b.x, b.y);
            }
        }

        // ---- epilogue: combine with x2 in-register, STG.128 direct ----
        #pragma unroll
        for (int p2 = 0; p2 < 2; p2++) {
            int grow = row0 + rl0 + 8 * p2;
            if (grow >= n) continue;
            float xs  = p2 ? xq1.x : xq0.x;
            float xv0 = p2 ? xq1.y : xq0.y;
            float xv1 = p2 ? xq1.z : xq0.z;
            float xv2 = p2 ? xq1.w : xq0.w;
            float os4[4], ov[12];
            #pragma unroll
            for (int wp = 0; wp < 4; wp++) {
                float y1 = acc1[wp][2 * p2 + 0];
                float y3 = acc1[wp][2 * p2 + 1];
                int s0i = 3 * wp,     t0 = s0i >> 1, j0 = s0i & 1;
                int s1i = 3 * wp + 1, t1 = s1i >> 1, j1 = s1i & 1;
                int s2i = 3 * wp + 2, t2 = s2i >> 1, j2 = s2i & 1;
                float y2a = acc2[0][t0][2 * p2 + j0];
                float y2b = acc2[1][t0][2 * p2 + j0];
                float y2c = acc2[2][t0][2 * p2 + j0];
                float y4a = acc2[0][t1][2 * p2 + j1];
                float y4b = acc2[1][t1][2 * p2 + j1];
                float y4c = acc2[2][t1][2 * p2 + j1];
                float y5a = acc2[0][t2][2 * p2 + j2];
                float y5b = acc2[1][t2][2 * p2 + j2];
                float y5c = acc2[2][t2][2 * p2 + j2];

                os4[wp] = xs * y1 + xv0 * y2a + xv1 * y2b + xv2 * y2c;
                ov[3 * wp + 0] = xv0 * y3 + xs * y4a + (y5b * xv2 - y5c * xv1);
                ov[3 * wp + 1] = xv1 * y3 + xs * y4b + (y5c * xv0 - y5a * xv2);
                ov[3 * wp + 2] = xv2 * y3 + xs * y4c + (y5a * xv1 - y5b * xv0);
            }
            float* orow = out + (size_t)grow * 256;
            *(float4*)(orow + wb) = make_float4(os4[0], os4[1], os4[2], os4[3]);
            *(float4*)(orow + 64 + 3 * wb + 0) =
                make_float4(ov[0], ov[1], ov[2], ov[3]);
            *(float4*)(orow + 64 + 3 * wb + 4) =
                make_float4(ov[4], ov[5], ov[6], ov[7]);
            *(float4*)(orow + 64 + 3 * wb + 8) =
                make_float4(ov[8], ov[9], ov[10], ov[11]);
        }
    }
}

extern "C" void kernel_launch(void* const* d_in, const int* in_sizes, int n_in,
                              void* d_out, int out_size) {
    const float* x1 = (const float*)d_in[0];
    const float* x2 = (const float*)d_in[1];
    const float* w1 = (const float*)d_in[2];   // w_ss_s
    const float* w2 = (const float*)d_in[3];   // w_vv_s
    const float* w3 = (const float*)d_in[4];   // w_sv_v
    const float* w4 = (const float*)d_in[5];   // w_vs_v
    const float* w5 = (const float*)d_in[6];   // w_vv_v
    float* out = (float*)d_out;

    int n = in_sizes[0] / 256;
    cudaFuncSetAttribute(tp_k, cudaFuncAttributeMaxDynamicSharedMemorySize,
                         SMEM_BYTES);
    int numTiles = (n + TILE - 1) / TILE;
    int grid = numTiles < 148 ? numTiles : 148;
    tp_k<<<grid, NTH, SMEM_BYTES>>>(x1, x2, w1, w2, w3, w4, w5, out, n);
}

// round 17
// speedup vs baseline: 1.4161x; 1.0003x over previous
#include <cuda_runtime.h>
#include <cuda_fp16.h>
#include <cstdint>

// TensorProduct, round 17: R16 (fp16 m16n8k16) with the CTA decoupled into
// THREE independent 128-thread slab pipelines. cp.async + repack are
// slab-aligned (each slab owns rows [16s,16s+16) of the tile) and the two
// global __syncthreads are replaced by named barriers (bar.sync 1+s, 128),
// so slabs drift out of phase and LSU-heavy repack overlaps tensor-heavy
// mainloop across slabs.
//   Y1  = x1s  @ [a0*W1 | a1*W3]               (K=64, N=128)
//   Y2k = x1vk @ [a0/s3*W2 | a1*W4 | a1/s2*W5]  (K=64, N=192; B shared over k)

#define NTH   384
#define TILE  48
#define AST   40                     // A-plane row stride (fp16x2 words)
#define BST   40                     // B row stride
#define PL    (TILE * AST)           // 1920

#define OFF_RAW 0
#define RAW_WORDS (TILE * 256)       // 12288
#define OFF_A   RAW_WORDS
#define OFF_B1  (OFF_A + 4 * PL)     // 19968
#define OFF_B2  (OFF_B1 + 128 * BST) // 25088
#define SMEM_WORDS (OFF_B2 + 192 * BST)   // 32768
#define SMEM_BYTES (SMEM_WORDS * 4)       // 131072

// storage position of k-pair j (=k>>1) within a row: groups of 8 words per
// 16 k's, order [0,4,1,5,2,6,3,7]
__device__ __forceinline__ int posj(int j) {
    return ((j >> 3) << 3) + ((j & 3) << 1) + ((j >> 2) & 1);
}
__device__ __forceinline__ uint32_t pack2(float lo, float hi) {
    __half2 h = __floats2half2_rn(lo, hi);
    return *reinterpret_cast<uint32_t*>(&h);
}
__device__ __forceinline__ uint32_t smem_u32(const void* p) {
    uint32_t a;
    asm("{ .reg .u64 t; cvta.to.shared.u64 t, %1; cvt.u32.u64 %0, t; }"
        : "=r"(a) : "l"(p));
    return a;
}
__device__ __forceinline__ void mma16(float* c, uint32_t a0, uint32_t a1,
                                      uint32_t a2, uint32_t a3,
                                      uint32_t b0, uint32_t b1) {
    asm volatile(
        "mma.sync.aligned.m16n8k16.row.col.f32.f16.f16.f32 "
        "{%0,%1,%2,%3}, {%4,%5,%6,%7}, {%8,%9}, {%0,%1,%2,%3};"
        : "+f"(c[0]), "+f"(c[1]), "+f"(c[2]), "+f"(c[3])
        : "r"(a0), "r"(a1), "r"(a2), "r"(a3), "r"(b0), "r"(b1));
}
__device__ __forceinline__ void cpa16(uint32_t dst, const void* src) {
    asm volatile("cp.async.cg.shared.global [%0], [%1], 16;"
                 :: "r"(dst), "l"(src));
}
__device__ __forceinline__ void slab_bar(int slab) {
    asm volatile("bar.sync %0, 128;" :: "r"(1 + slab) : "memory");
}

__global__ __launch_bounds__(NTH, 1)
void tp_k(const float* __restrict__ x1, const float* __restrict__ x2,
          const float* __restrict__ w1, const float* __restrict__ w2,
          const float* __restrict__ w3, const float* __restrict__ w4,
          const float* __restrict__ w5,
          float* __restrict__ out, int n) {
    extern __shared__ uint32_t sw[];
    const int tid  = threadIdx.x;
    const int lane = tid & 31;
    const int wid  = tid >> 5;
    const int q    = lane & 3;
    const int rsub = lane >> 2;          // 0..7
    const int slab = wid >> 2;           // 0..2  (owns rows [16*slab,16*slab+16))
    const int qd   = wid & 3;            // w-quarter: w in [16qd, 16qd+16)
    const int st   = tid & 127;          // thread id within slab

    const float A0   = 0.08838834764831845f;   // sqrt(1/128)
    const float A0S3 = 0.05103103630798288f;   // a0/sqrt(3)
    const float A1   = 0.07216878364870323f;   // sqrt(1/192)
    const float A1R2 = 0.05103103630798288f;   // a1/sqrt(2)

    const int numTiles = (n + TILE - 1) / TILE;
    const uint32_t sbRaw = smem_u32(sw + OFF_RAW);
    const int srow0 = slab * 16;         // slab's first local row

    // ---- prologue: cp.async first tile (slab-aligned rows) ----
    {
        int row0 = blockIdx.x * TILE;
        #pragma unroll
        for (int it = 0; it < 8; it++) {
            int idx = st + it * 128;                // 1024 chunks per slab
            int rl = srow0 + (idx >> 6), c = (idx & 63) << 2;
            int grow = row0 + rl; if (grow >= n) grow = 0;
            cpa16(sbRaw + ((rl * 256 + c) << 2), x1 + (size_t)grow * 256 + c);
        }
    }
    asm volatile("cp.async.commit_group;" ::: "memory");

    // ---- stage B (fp16 pairs, n-permuted, k-pair-permuted) ----
    for (int i = tid; i < 128 * 32; i += NTH) {
        int nn = i >> 5, j = i & 31;
        int qdd = nn >> 5, nl = nn & 31;
        int wp = nl >> 3, rem = nl & 7, qq = rem >> 1, m = rem & 1;
        int w = 16 * qdd + 4 * qq + wp;
        int k0 = 2 * j, k1 = 2 * j + 1;
        float vlo = m ? A1 * w3[k0 * 64 + w] : A0 * w1[k0 * 64 + w];
        float vhi = m ? A1 * w3[k1 * 64 + w] : A0 * w1[k1 * 64 + w];
        sw[OFF_B1 + nn * BST + posj(j)] = pack2(vlo, vhi);
    }
    for (int i = tid; i < 192 * 32; i += NTH) {
        int nn = i >> 5, j = i & 31;
        int qdd = nn / 48, nl = nn - 48 * qdd;
        int t = nl >> 3, rem = nl & 7, qq = rem >> 1, jj = rem & 1;
        int s = 2 * t + jj, wp = s / 3, m = s - 3 * wp;
        int w = 16 * qdd + 4 * qq + wp;
        int k0 = 2 * j, k1 = 2 * j + 1;
        float sc = (m == 0) ? A0S3 : (m == 1) ? A1 : A1R2;
        const float* W = (m == 0) ? w2 : (m == 1) ? w4 : w5;
        sw[OFF_B2 + nn * BST + posj(j)] = pack2(sc * W[k0 * 64 + w],
                                                sc * W[k1 * 64 + w]);
    }
    __syncthreads();   // B visible to every slab (only global sync)

    const int rl0 = srow0 + rsub;
    const int wb  = 16 * qd + 4 * q;
    const uint32_t* aS  = sw + OFF_A + rl0 * AST + 2 * q;
    const uint32_t* b1p = sw + OFF_B1 + (32 * qd + rsub) * BST + 2 * q;
    const uint32_t* b2p = sw + OFF_B2 + (48 * qd + rsub) * BST + 2 * q;
    const float* rawf = (const float*)(sw + OFF_RAW);

    for (int tile = blockIdx.x; tile < numTiles; tile += gridDim.x) {
        const int row0 = tile * TILE;

        // ---- wait this slab's raw; slab barrier (also: planes of t-1 free) ----
        asm volatile("cp.async.wait_group 0;" ::: "memory");
        slab_bar(slab);

        float4 xq0 = make_float4(0.f, 0.f, 0.f, 0.f), xq1 = xq0;
        if (row0 + rl0 < n)     xq0 = *(const float4*)(x2 + (size_t)(row0 + rl0) * 4);
        if (row0 + rl0 + 8 < n) xq1 = *(const float4*)(x2 + (size_t)(row0 + rl0 + 8) * 4);

        // ---- repack this slab's 16 rows into fp16 planes ----
        #pragma unroll
        for (int it = 0; it < 4; it++) {
            int task = st + it * 128;            // 512 = 16 rows x 32 j
            int r = srow0 + (task >> 5), j = task & 31;
            const float* rp = rawf + r * 256;
            float s0 = rp[2 * j], s1 = rp[2 * j + 1];
            float b0 = rp[64 + 6 * j + 0], b1 = rp[64 + 6 * j + 1];
            float b2 = rp[64 + 6 * j + 2], b3 = rp[64 + 6 * j + 3];
            float b4 = rp[64 + 6 * j + 4], b5 = rp[64 + 6 * j + 5];
            int ao = r * AST + posj(j);
            sw[OFF_A + 0 * PL + ao] = pack2(s0, s1);   // scalar plane
            sw[OFF_A + 1 * PL + ao] = pack2(b0, b3);   // v component 0
            sw[OFF_A + 2 * PL + ao] = pack2(b1, b4);   // v component 1
            sw[OFF_A + 3 * PL + ao] = pack2(b2, b5);   // v component 2
        }
        slab_bar(slab);   // planes(t) ready; slab's raw rows free

        // ---- issue next tile's cp.async for this slab's rows ----
        int ntile = tile + gridDim.x;
        if (ntile < numTiles) {
            int nrow0 = ntile * TILE;
            #pragma unroll
            for (int it = 0; it < 8; it++) {
                int idx = st + it * 128;
                int rl = srow0 + (idx >> 6), c = (idx & 63) << 2;
                int grow = nrow0 + rl; if (grow >= n) grow = 0;
                cpa16(sbRaw + ((rl * 256 + c) << 2), x1 + (size_t)grow * 256 + c);
            }
        }
        asm volatile("cp.async.commit_group;" ::: "memory");

        // ---- mainloop: 4 k16-steps, 22 mma each ----
        float acc1[4][4];
        float acc2[3][6][4];
        #pragma unroll
        for (int t = 0; t < 4; t++)
            #pragma unroll
            for (int c = 0; c < 4; c++) acc1[t][c] = 0.f;
        #pragma unroll
        for (int kv = 0; kv < 3; kv++)
            #pragma unroll
            for (int t = 0; t < 6; t++)
                #pragma unroll
                for (int c = 0; c < 4; c++) acc2[kv][t][c] = 0.f;

        #pragma unroll
        for (int g = 0; g < 4; g++) {
            uint2 s0 = *(const uint2*)(aS + g * 8);
            uint2 s1 = *(const uint2*)(aS + 8 * AST + g * 8);
            uint2 vl[3], vh[3];
            #pragma unroll
            for (int kv = 0; kv < 3; kv++) {
                vl[kv] = *(const uint2*)(aS + (kv + 1) * PL + g * 8);
                vh[kv] = *(const uint2*)(aS + (kv + 1) * PL + 8 * AST + g * 8);
            }
            #pragma unroll
            for (int t = 0; t < 4; t++) {
                uint2 b = *(const uint2*)(b1p + t * 8 * BST + g * 8);
                mma16(acc1[t], s0.x, s1.x, s0.y, s1.y, b.x, b.y);
            }
            #pragma unroll
            for (int t = 0; t < 6; t++) {
                uint2 b = *(const uint2*)(b2p + t * 8 * BST + g * 8);
                mma16(acc2[0][t], vl[0].x, vh[0].x, vl[0].y, vh[0].y, b.x, b.y);
                mma16(acc2[1][t], vl[1].x, vh[1].x, vl[1].y, vh[1].y, b.x, b.y);
                mma16(acc2[2][t], vl[2].x, vh[2].x, vl[2].y, vh[2].y, b.x, b.y);
            }
        }

        // ---- epilogue: combine with x2 in-register, STG.128 direct ----
        #pragma unroll
        for (int p2 = 0; p2 < 2; p2++) {
            int grow = row0 + rl0 + 8 * p2;
            if (grow >= n) continue;
            float xs  = p2 ? xq1.x : xq0.x;
            float xv0 = p2 ? xq1.y : xq0.y;
            float xv1 = p2 ? xq1.z : xq0.z;
            float xv2 = p2 ? xq1.w : xq0.w;
            float os4[4], ov[12];
            #pragma unroll
            for (int wp = 0; wp < 4; wp++) {
                float y1 = acc1[wp][2 * p2 + 0];
                float y3 = acc1[wp][2 * p2 + 1];
                int s0i = 3 * wp,     t0 = s0i >> 1, j0 = s0i & 1;
                int s1i = 3 * wp + 1, t1 = s1i >> 1, j1 = s1i & 1;
                int s2i = 3 * wp + 2, t2 = s2i >> 1, j2 = s2i & 1;
                float y2a = acc2[0][t0][2 * p2 + j0];
                float y2b = acc2[1][t0][2 * p2 + j0];
                float y2c = acc2[2][t0][2 * p2 + j0];
                float y4a = acc2[0][t1][2 * p2 + j1];
                float y4b = acc2[1][t1][2 * p2 + j1];
                float y4c = acc2[2][t1][2 * p2 + j1];
                float y5a = acc2[0][t2][2 * p2 + j2];
                float y5b = acc2[1][t2][2 * p2 + j2];
                float y5c = acc2[2][t2][2 * p2 + j2];

                os4[wp] = xs * y1 + xv0 * y2a + xv1 * y2b + xv2 * y2c;
                ov[3 * wp + 0] = xv0 * y3 + xs * y4a + (y5b * xv2 - y5c * xv1);
                ov[3 * wp + 1] = xv1 * y3 + xs * y4b + (y5c * xv0 - y5a * xv2);
                ov[3 * wp + 2] = xv2 * y3 + xs * y4c + (y5a * xv1 - y5b * xv0);
            }
            float* orow = out + (size_t)grow * 256;
            *(float4*)(orow + wb) = make_float4(os4[0], os4[1], os4[2], os4[3]);
            *(float4*)(orow + 64 + 3 * wb + 0) =
                make_float4(ov[0], ov[1], ov[2], ov[3]);
            *(float4*)(orow + 64 + 3 * wb + 4) =
                make_float4(ov[4], ov[5], ov[6], ov[7]);
            *(float4*)(orow + 64 + 3 * wb + 8) =
                make_float4(ov[8], ov[9], ov[10], ov[11]);
        }
    }
}

extern "C" void kernel_launch(void* const* d_in, const int* in_sizes, int n_in,
                              void* d_out, int out_size) {
    const float* x1 = (const float*)d_in[0];
    const float* x2 = (const float*)d_in[1];
    const float* w1 = (const float*)d_in[2];   // w_ss_s
    const float* w2 = (const float*)d_in[3];   // w_vv_s
    const float* w3 = (const float*)d_in[4];   // w_sv_v
    const float* w4 = (const float*)d_in[5];   // w_vs_v
    const float* w5 = (const float*)d_in[6];   // w_vv_v
    float* out = (float*)d_out;

    int n = in_sizes[0] / 256;
    cudaFuncSetAttribute(tp_k, cudaFuncAttributeMaxDynamicSharedMemorySize,
                         SMEM_BYTES);
    int numTiles = (n + TILE - 1) / TILE;
    int grid = numTiles < 148 ? numTiles : 148;
    tp_k<<<grid, NTH, SMEM_BYTES>>>(x1, x2, w1, w2, w3, w4, w5, out, n);
}